// round 4
// baseline (speedup 1.0000x reference)
#include <cuda_runtime.h>
#include <math.h>

// ---------------------------------------------------------------------------
// SinkhornNetwork on GB300 — round 0: correct fp32 pipeline.
//   M = B*N = 512*36 = 18432 rows
//   seq row layout: [0:512) txt | [512:2560) vis | [2560:2564) pos | [2564:3076) sen
// Stages:
//   vis1 : [M,2048] @ W1_vis^T  -> relu -> g_vis1 [M,512]
//   txt  : [M,512]  @ W1_txt^T  -> relu -> g_cat[:,0:128)
//   vis2 : g_vis1   @ W2_vis^T  -> relu -> g_cat[:,128:256)
//   pos  : relu(seq[...,2560:2564])    -> g_cat[:,256:260)
//   sen  : [M,512]  @ W1_sen^T  -> relu -> g_cat[:,260:388)
//   fcp  : g_cat    @ Wfcpos^T  -> relu -> g_h256 [M,256]
//   fc   : g_h256   @ Wfc^T     -> tanh -> g_logits [M,36]
//   sinkhorn(512 x 36x36, 20 iters)    -> d_out
// ---------------------------------------------------------------------------

#define BM 128
#define BN 128
#define BKK 16
#define TM 8
#define TN 8

static constexpr int MROWS = 512 * 36;   // 18432

__device__ float g_vis1[MROWS * 512];
__device__ float g_cat [MROWS * 388];
__device__ float g_h256[MROWS * 256];
__device__ float g_logits[MROWS * 36];

// Classic fp32 blocktile SGEMM: C[M,N] = act(A[M,K] * W[N,K]^T + bias)
// A row-major with stride lda; W row-major [N,K]; C row-major stride ldc.
// Requires: M % BM == 0, N % BN == 0, K % 4 == 0, all pointers 16B aligned.
template<bool RELU>
__global__ void __launch_bounds__(256) sgemm_bias_act(
    const float* __restrict__ A, int lda,
    const float* __restrict__ W,
    const float* __restrict__ bias,
    float* __restrict__ C, int ldc,
    int K)
{
    __shared__ float As[BKK][BM + 4];
    __shared__ float Bs[BKK][BN + 4];

    const int tid  = threadIdx.x;
    const int tcol = tid & 15;    // 0..15
    const int trow = tid >> 4;    // 0..15
    const long bm  = (long)blockIdx.y * BM;
    const long bn  = (long)blockIdx.x * BN;

    const int lr = tid >> 2;      // 0..63
    const int lc = tid & 3;       // float4 col within BK

    const float* Ap = A + bm * (long)lda;
    const float* Wp = W + bn * (long)K;

    float acc[TM][TN];
    #pragma unroll
    for (int i = 0; i < TM; i++)
        #pragma unroll
        for (int j = 0; j < TN; j++)
            acc[i][j] = 0.0f;

    for (int k0 = 0; k0 < K; k0 += BKK) {
        const int kk = k0 + lc * 4;
        const bool kval = (kk + 4 <= K);

        // Load A tile (BM x BK), store transposed As[k][m]
        #pragma unroll
        for (int r = 0; r < BM; r += 64) {
            float4 v = make_float4(0.f, 0.f, 0.f, 0.f);
            if (kval)
                v = *reinterpret_cast<const float4*>(Ap + (long)(lr + r) * lda + kk);
            As[lc * 4 + 0][lr + r] = v.x;
            As[lc * 4 + 1][lr + r] = v.y;
            As[lc * 4 + 2][lr + r] = v.z;
            As[lc * 4 + 3][lr + r] = v.w;
        }
        // Load W tile (BN x BK), store transposed Bs[k][n]
        #pragma unroll
        for (int r = 0; r < BN; r += 64) {
            float4 v = make_float4(0.f, 0.f, 0.f, 0.f);
            if (kval)
                v = *reinterpret_cast<const float4*>(Wp + (long)(lr + r) * K + kk);
            Bs[lc * 4 + 0][lr + r] = v.x;
            Bs[lc * 4 + 1][lr + r] = v.y;
            Bs[lc * 4 + 2][lr + r] = v.z;
            Bs[lc * 4 + 3][lr + r] = v.w;
        }
        __syncthreads();

        #pragma unroll
        for (int k = 0; k < BKK; k++) {
            float am[TM], wn[TN];
            *reinterpret_cast<float4*>(&am[0]) =
                *reinterpret_cast<const float4*>(&As[k][trow * TM]);
            *reinterpret_cast<float4*>(&am[4]) =
                *reinterpret_cast<const float4*>(&As[k][trow * TM + 4]);
            *reinterpret_cast<float4*>(&wn[0]) =
                *reinterpret_cast<const float4*>(&Bs[k][tcol * TN]);
            *reinterpret_cast<float4*>(&wn[4]) =
                *reinterpret_cast<const float4*>(&Bs[k][tcol * TN + 4]);
            #pragma unroll
            for (int i = 0; i < TM; i++)
                #pragma unroll
                for (int j = 0; j < TN; j++)
                    acc[i][j] = fmaf(am[i], wn[j], acc[i][j]);
        }
        __syncthreads();
    }

    // Epilogue: bias + activation, vectorized stores
    #pragma unroll
    for (int i = 0; i < TM; i++) {
        const long row = bm + trow * TM + i;
        #pragma unroll
        for (int j = 0; j < TN; j += 4) {
            const long col = bn + tcol * TN + j;
            float4 o;
            o.x = acc[i][j + 0] + __ldg(&bias[col + 0]);
            o.y = acc[i][j + 1] + __ldg(&bias[col + 1]);
            o.z = acc[i][j + 2] + __ldg(&bias[col + 2]);
            o.w = acc[i][j + 3] + __ldg(&bias[col + 3]);
            if (RELU) {
                o.x = fmaxf(o.x, 0.f); o.y = fmaxf(o.y, 0.f);
                o.z = fmaxf(o.z, 0.f); o.w = fmaxf(o.w, 0.f);
            }
            *reinterpret_cast<float4*>(C + row * (long)ldc + col) = o;
        }
    }
}

// relu(seq[...,2560:2564]) -> g_cat[:,256:260)
__global__ void pos_relu_kernel(const float* __restrict__ seq, float* __restrict__ cat)
{
    int idx = blockIdx.x * blockDim.x + threadIdx.x;
    if (idx < MROWS * 4) {
        int r = idx >> 2, c = idx & 3;
        float v = seq[(long)r * 3076 + 2560 + c];
        cat[(long)r * 388 + 256 + c] = fmaxf(v, 0.f);
    }
}

// Final fc: [M,256] @ W[36,256]^T + b -> tanh -> logits [M,36]
// 8 rows per block, 288 threads (r = t/36, n = t%36).
__global__ void __launch_bounds__(288) fc_tanh_kernel(
    const float* __restrict__ A,
    const float* __restrict__ W,
    const float* __restrict__ bias,
    float* __restrict__ out)
{
    __shared__ float Ws[36 * 260];
    __shared__ float Asm[8 * 260];
    __shared__ float bs[36];

    const int tid = threadIdx.x;
    const long rowBase = (long)blockIdx.x * 8;

    for (int i = tid; i < 36 * 256; i += 288) {
        int n = i >> 8, k = i & 255;
        Ws[n * 260 + k] = W[i];
    }
    for (int i = tid; i < 8 * 256; i += 288) {
        int r = i >> 8, k = i & 255;
        Asm[r * 260 + k] = A[(rowBase + r) * 256 + k];
    }
    if (tid < 36) bs[tid] = bias[tid];
    __syncthreads();

    const int r = tid / 36;
    const int n = tid % 36;
    if (r < 8) {
        const float* a = &Asm[r * 260];
        const float* w = &Ws[n * 260];
        float s = bs[n];
        #pragma unroll 8
        for (int k = 0; k < 256; k++)
            s = fmaf(a[k], w[k], s);
        out[(rowBase + r) * 36 + n] = tanhf(s);
    }
}

// Sinkhorn: per batch matrix (36x36), 20 iterations of row-LSE then col-LSE,
// matching the reference: y0 = exp(t/0.05); iter: y -= lse(y,-1); y -= lse(y,-2);
// return exp(y). Thread j owns column j (registers); row LSE via smem.
__global__ void __launch_bounds__(64) sinkhorn_kernel(
    const float* __restrict__ logits, float* __restrict__ out)
{
    const int b = blockIdx.x;
    const int j = threadIdx.x;
    __shared__ float xm[36][37];
    __shared__ float rowlse[36];
    float col[36];
    const bool act = (j < 36);

    if (act) {
        #pragma unroll
        for (int i = 0; i < 36; i++) {
            float t = logits[((long)b * 36 + i) * 36 + j];
            col[i] = expf(t * 20.0f);      // exp(x / 0.05)
        }
    }

    for (int it = 0; it < 20; it++) {
        if (act) {
            #pragma unroll
            for (int i = 0; i < 36; i++) xm[i][j] = col[i];
        }
        __syncthreads();
        if (act) {
            // LSE over columns of row j
            float m = -INFINITY;
            #pragma unroll
            for (int k = 0; k < 36; k++) m = fmaxf(m, xm[j][k]);
            float s = 0.f;
            #pragma unroll
            for (int k = 0; k < 36; k++) s += expf(xm[j][k] - m);
            rowlse[j] = m + logf(s);
        }
        __syncthreads();
        if (act) {
            #pragma unroll
            for (int i = 0; i < 36; i++) col[i] -= rowlse[i];
            // LSE over rows of my column (local registers)
            float m = -INFINITY;
            #pragma unroll
            for (int i = 0; i < 36; i++) m = fmaxf(m, col[i]);
            float s = 0.f;
            #pragma unroll
            for (int i = 0; i < 36; i++) s += expf(col[i] - m);
            float l = m + logf(s);
            #pragma unroll
            for (int i = 0; i < 36; i++) col[i] -= l;
        }
        __syncthreads();
    }

    if (act) {
        #pragma unroll
        for (int i = 0; i < 36; i++)
            out[((long)b * 36 + i) * 36 + j] = expf(col[i]);
    }
}

extern "C" void kernel_launch(void* const* d_in, const int* in_sizes, int n_in,
                              void* d_out, int out_size)
{
    const float* seq      = (const float*)d_in[0];
    const float* W1_txt_w = (const float*)d_in[1];
    const float* W1_txt_b = (const float*)d_in[2];
    const float* W1_vis_w = (const float*)d_in[3];
    const float* W1_vis_b = (const float*)d_in[4];
    const float* W2_vis_w = (const float*)d_in[5];
    const float* W2_vis_b = (const float*)d_in[6];
    const float* W1_sen_w = (const float*)d_in[7];
    const float* W1_sen_b = (const float*)d_in[8];
    const float* Wfcp_w   = (const float*)d_in[9];
    const float* Wfcp_b   = (const float*)d_in[10];
    const float* Wfc_w    = (const float*)d_in[11];
    const float* Wfc_b    = (const float*)d_in[12];
    float* out = (float*)d_out;

    float *p_vis1, *p_cat, *p_h256, *p_logits;
    cudaGetSymbolAddress((void**)&p_vis1,   g_vis1);
    cudaGetSymbolAddress((void**)&p_cat,    g_cat);
    cudaGetSymbolAddress((void**)&p_h256,   g_h256);
    cudaGetSymbolAddress((void**)&p_logits, g_logits);

    const int gy = MROWS / BM;   // 144

    // vis1: [M,2048] -> [M,512]
    sgemm_bias_act<true><<<dim3(512 / BN, gy), 256>>>(
        seq + 512, 3076, W1_vis_w, W1_vis_b, p_vis1, 512, 2048);

    // txt: [M,512] -> cat[:,0:128)
    sgemm_bias_act<true><<<dim3(1, gy), 256>>>(
        seq + 0, 3076, W1_txt_w, W1_txt_b, p_cat + 0, 388, 512);

    // vis2: [M,512] -> cat[:,128:256)
    sgemm_bias_act<true><<<dim3(1, gy), 256>>>(
        p_vis1, 512, W2_vis_w, W2_vis_b, p_cat + 128, 388, 512);

    // sen: [M,512] -> cat[:,260:388)
    sgemm_bias_act<true><<<dim3(1, gy), 256>>>(
        seq + 2564, 3076, W1_sen_w, W1_sen_b, p_cat + 260, 388, 512);

    // pos: relu -> cat[:,256:260)
    pos_relu_kernel<<<(MROWS * 4 + 255) / 256, 256>>>(seq, p_cat);

    // fc_pos: [M,388] -> [M,256]
    sgemm_bias_act<true><<<dim3(256 / BN, gy), 256>>>(
        p_cat, 388, Wfcp_w, Wfcp_b, p_h256, 256, 388);

    // fc: [M,256] -> [M,36], tanh
    fc_tanh_kernel<<<MROWS / 8, 288>>>(p_h256, Wfc_w, Wfc_b, p_logits);

    // sinkhorn
    sinkhorn_kernel<<<512, 64>>>(p_logits, out);
}

// round 10
// speedup vs baseline: 2.2514x; 2.2514x over previous
#include <cuda_runtime.h>
#include <cuda_fp16.h>
#include <math.h>
#include <stdint.h>

// ---------------------------------------------------------------------------
// SinkhornNetwork on GB300 — round 8: mma.sync fp16-split GEMMs (Ootomo).
//   C = Ah*Wh + Al*Wh + Ah*Wl  (fp32 accumulate), fp16 hi/lo split captures
//   ~24 mantissa bits -> fp32-quality results at tensor-core speed.
//   W is scaled x32 at conversion (residuals stay fp16-normal); epilogue
//   multiplies by 1/32.
// ---------------------------------------------------------------------------

static constexpr int MROWS = 512 * 36;   // 18432

__device__ float g_vis1[MROWS * 512];
__device__ float g_cat [MROWS * 388];
__device__ float g_h256[MROWS * 256];
__device__ float g_logits[MROWS * 36];

// ---------------- helpers ----------------

__device__ __forceinline__ uint32_t smem_u32(const void* p) {
    uint32_t a;
    asm("{ .reg .u64 t; cvta.to.shared.u64 t, %1; cvt.u32.u64 %0, t; }"
        : "=r"(a) : "l"(p));
    return a;
}

__device__ __forceinline__ void ldm4(uint32_t* d, uint32_t a) {
    asm volatile("ldmatrix.sync.aligned.m8n8.x4.shared.b16 {%0,%1,%2,%3}, [%4];"
        : "=r"(d[0]), "=r"(d[1]), "=r"(d[2]), "=r"(d[3]) : "r"(a));
}

__device__ __forceinline__ void mma16816(float* c, const uint32_t* a, const uint32_t* b) {
    asm volatile(
        "mma.sync.aligned.m16n8k16.row.col.f32.f16.f16.f32 "
        "{%0,%1,%2,%3},{%4,%5,%6,%7},{%8,%9},{%0,%1,%2,%3};"
        : "+f"(c[0]), "+f"(c[1]), "+f"(c[2]), "+f"(c[3])
        : "r"(a[0]), "r"(a[1]), "r"(a[2]), "r"(a[3]), "r"(b[0]), "r"(b[1]));
}

// fp16 split of two floats: hi = packed {lo16=f16(a), hi16=f16(b)},
// lo = packed residuals. cvt.f16x2 packs first operand into the UPPER half.
__device__ __forceinline__ void split2h(float a, float b, uint32_t& hi, uint32_t& lo) {
    uint32_t h;
    asm("cvt.rn.f16x2.f32 %0, %1, %2;" : "=r"(h) : "f"(b), "f"(a));
    float2 hf = __half22float2(*reinterpret_cast<const __half2*>(&h));
    float ra = a - hf.x;         // low half holds a
    float rb = b - hf.y;
    uint32_t l;
    asm("cvt.rn.f16x2.f32 %0, %1, %2;" : "=r"(l) : "f"(rb), "f"(ra));
    hi = h; lo = l;
}

// ---------------- mma.sync GEMM ----------------
// C[128 x 128] tile = relu((A*W^T)*1/32 + bias), W pre-scaled x32.
// grid = (N/128, M/128), 256 threads (8 warps, 4(m) x 2(n)).
// smem per stage: Ahi, Alo, Whi, Wlo — 128 rows x 32 fp16 (64B), padded to 80B.

static constexpr int   ROWB   = 80;
static constexpr int   TILEB  = 128 * ROWB;     // 10240
static constexpr int   STAGEB = 4 * TILEB;      // 40960
static constexpr int   SMEMB  = 2 * STAGEB;     // 81920
static constexpr float WSCALE = 32.0f;
static constexpr float WINV   = 1.0f / 32.0f;

__global__ void __launch_bounds__(256, 1) mma_gemm(
    const float* __restrict__ A, int lda,
    const float* __restrict__ W,
    const float* __restrict__ bias,
    float* __restrict__ C, int ldc,
    int K, int nch)
{
    extern __shared__ char sm[];
    const uint32_t sbase = smem_u32(sm);

    const int tid  = threadIdx.x;
    const int lane = tid & 31;
    const int w    = tid >> 5;
    const int wm   = w & 3;        // warp row (x32)
    const int wn   = w >> 2;       // warp col (x64)
    const long bm  = (long)blockIdx.y * 128;
    const long bn  = (long)blockIdx.x * 128;

    const float* Ap = A + bm * (long)lda;
    const float* Wp = W + bn * (long)K;

    float acc[2][8][4];
    #pragma unroll
    for (int mt = 0; mt < 2; mt++)
        #pragma unroll
        for (int nt = 0; nt < 8; nt++)
            #pragma unroll
            for (int q = 0; q < 4; q++)
                acc[mt][nt][q] = 0.0f;

    float4 ar[4], wr[4];   // staging registers for next chunk

    auto LDG = [&](int kc) {
        const int k0 = kc * 32;
        #pragma unroll
        for (int it = 0; it < 4; it++) {
            int idx = tid + it * 256;
            int row = idx >> 3;
            int k   = k0 + ((idx & 7) << 2);
            if (k + 4 <= K) {
                ar[it] = *reinterpret_cast<const float4*>(Ap + (size_t)row * lda + k);
                wr[it] = *reinterpret_cast<const float4*>(Wp + (size_t)row * K + k);
            } else {
                ar[it] = make_float4(0.f, 0.f, 0.f, 0.f);
                wr[it] = make_float4(0.f, 0.f, 0.f, 0.f);
            }
        }
    };

    auto STS = [&](int stg) {
        char* s = sm + stg * STAGEB;
        #pragma unroll
        for (int it = 0; it < 4; it++) {
            int idx = tid + it * 256;
            int row = idx >> 3;
            int c4  = (idx & 7) << 2;
            int off = row * ROWB + (c4 << 1);
            uint32_t h0, l0, h1, l1;
            split2h(ar[it].x, ar[it].y, h0, l0);
            split2h(ar[it].z, ar[it].w, h1, l1);
            *reinterpret_cast<uint2*>(s + off)             = make_uint2(h0, h1); // Ahi
            *reinterpret_cast<uint2*>(s + TILEB + off)     = make_uint2(l0, l1); // Alo
            split2h(wr[it].x * WSCALE, wr[it].y * WSCALE, h0, l0);
            split2h(wr[it].z * WSCALE, wr[it].w * WSCALE, h1, l1);
            *reinterpret_cast<uint2*>(s + 2 * TILEB + off) = make_uint2(h0, h1); // Whi
            *reinterpret_cast<uint2*>(s + 3 * TILEB + off) = make_uint2(l0, l1); // Wlo
        }
    };

    const int r8 = lane & 7;
    const int g  = lane >> 3;
    auto COMP = [&](int stg) {
        const uint32_t sb = sbase + (uint32_t)stg * STAGEB;
        #pragma unroll
        for (int s = 0; s < 2; s++) {       // two k16 steps per 32-col chunk
            uint32_t ah[2][4], al[2][4];
            #pragma unroll
            for (int mt = 0; mt < 2; mt++) {
                int row = wm * 32 + mt * 16 + ((g & 1) << 3) + r8;
                int co  = (s * 16 + ((g >> 1) << 3)) << 1;
                ldm4(ah[mt], sb + row * ROWB + co);
                ldm4(al[mt], sb + TILEB + row * ROWB + co);
            }
            uint32_t bh[8][2], bl[8][2];
            #pragma unroll
            for (int np = 0; np < 4; np++) {
                int row = wn * 64 + np * 16 + ((g >> 1) << 3) + r8;
                int co  = (s * 16 + ((g & 1) << 3)) << 1;
                uint32_t q[4];
                ldm4(q, sb + 2 * TILEB + row * ROWB + co);
                bh[np * 2][0] = q[0]; bh[np * 2][1] = q[1];
                bh[np * 2 + 1][0] = q[2]; bh[np * 2 + 1][1] = q[3];
                ldm4(q, sb + 3 * TILEB + row * ROWB + co);
                bl[np * 2][0] = q[0]; bl[np * 2][1] = q[1];
                bl[np * 2 + 1][0] = q[2]; bl[np * 2 + 1][1] = q[3];
            }
            #pragma unroll
            for (int mt = 0; mt < 2; mt++)
                #pragma unroll
                for (int nt = 0; nt < 8; nt++) {
                    mma16816(acc[mt][nt], ah[mt], bh[nt]);   // hi*hi
                    mma16816(acc[mt][nt], al[mt], bh[nt]);   // lo*hi
                    mma16816(acc[mt][nt], ah[mt], bl[nt]);   // hi*lo
                }
        }
    };

    LDG(0);
    STS(0);
    __syncthreads();
    for (int i = 0; i < nch; i++) {
        if (i + 1 < nch) LDG(i + 1);
        COMP(i & 1);
        __syncthreads();
        if (i + 1 < nch) { STS((i + 1) & 1); __syncthreads(); }
    }

    // epilogue: *1/32, + bias, relu
    #pragma unroll
    for (int mt = 0; mt < 2; mt++) {
        const long r0 = bm + wm * 32 + mt * 16 + (lane >> 2);
        #pragma unroll
        for (int nt = 0; nt < 8; nt++) {
            const long col = bn + wn * 64 + nt * 8 + (lane & 3) * 2;
            float2 bv = *reinterpret_cast<const float2*>(bias + col);
            float2 o0, o1;
            o0.x = fmaxf(fmaf(acc[mt][nt][0], WINV, bv.x), 0.f);
            o0.y = fmaxf(fmaf(acc[mt][nt][1], WINV, bv.y), 0.f);
            o1.x = fmaxf(fmaf(acc[mt][nt][2], WINV, bv.x), 0.f);
            o1.y = fmaxf(fmaf(acc[mt][nt][3], WINV, bv.y), 0.f);
            *reinterpret_cast<float2*>(C + r0 * (long)ldc + col)       = o0;
            *reinterpret_cast<float2*>(C + (r0 + 8) * (long)ldc + col) = o1;
        }
    }
}

// ---------------- small kernels (unchanged from passing round) ----------------

__global__ void pos_relu_kernel(const float* __restrict__ seq, float* __restrict__ cat)
{
    int idx = blockIdx.x * blockDim.x + threadIdx.x;
    if (idx < MROWS * 4) {
        int r = idx >> 2, c = idx & 3;
        float v = seq[(long)r * 3076 + 2560 + c];
        cat[(long)r * 388 + 256 + c] = fmaxf(v, 0.f);
    }
}

__global__ void __launch_bounds__(288) fc_tanh_kernel(
    const float* __restrict__ A,
    const float* __restrict__ W,
    const float* __restrict__ bias,
    float* __restrict__ out)
{
    __shared__ float Ws[36 * 260];
    __shared__ float Asm[8 * 260];
    __shared__ float bs[36];

    const int tid = threadIdx.x;
    const long rowBase = (long)blockIdx.x * 8;

    for (int i = tid; i < 36 * 256; i += 288) {
        int n = i >> 8, k = i & 255;
        Ws[n * 260 + k] = W[i];
    }
    for (int i = tid; i < 8 * 256; i += 288) {
        int r = i >> 8, k = i & 255;
        Asm[r * 260 + k] = A[(rowBase + r) * 256 + k];
    }
    if (tid < 36) bs[tid] = bias[tid];
    __syncthreads();

    const int r = tid / 36;
    const int n = tid % 36;
    if (r < 8) {
        const float* a = &Asm[r * 260];
        const float* wv = &Ws[n * 260];
        float s = bs[n];
        #pragma unroll 8
        for (int k = 0; k < 256; k++)
            s = fmaf(a[k], wv[k], s);
        out[(rowBase + r) * 36 + n] = tanhf(s);
    }
}

__global__ void __launch_bounds__(64) sinkhorn_kernel(
    const float* __restrict__ logits, float* __restrict__ out)
{
    const int b = blockIdx.x;
    const int j = threadIdx.x;
    __shared__ float xm[36][37];
    __shared__ float rowlse[36];
    float col[36];
    const bool act = (j < 36);

    if (act) {
        #pragma unroll
        for (int i = 0; i < 36; i++) {
            float t = logits[((long)b * 36 + i) * 36 + j];
            col[i] = expf(t * 20.0f);
        }
    }

    for (int it = 0; it < 20; it++) {
        if (act) {
            #pragma unroll
            for (int i = 0; i < 36; i++) xm[i][j] = col[i];
        }
        __syncthreads();
        if (act) {
            float m = -INFINITY;
            #pragma unroll
            for (int k = 0; k < 36; k++) m = fmaxf(m, xm[j][k]);
            float s = 0.f;
            #pragma unroll
            for (int k = 0; k < 36; k++) s += expf(xm[j][k] - m);
            rowlse[j] = m + logf(s);
        }
        __syncthreads();
        if (act) {
            #pragma unroll
            for (int i = 0; i < 36; i++) col[i] -= rowlse[i];
            float m = -INFINITY;
            #pragma unroll
            for (int i = 0; i < 36; i++) m = fmaxf(m, col[i]);
            float s = 0.f;
            #pragma unroll
            for (int i = 0; i < 36; i++) s += expf(col[i] - m);
            float l = m + logf(s);
            #pragma unroll
            for (int i = 0; i < 36; i++) col[i] -= l;
        }
        __syncthreads();
    }

    if (act) {
        #pragma unroll
        for (int i = 0; i < 36; i++)
            out[((long)b * 36 + i) * 36 + j] = expf(col[i]);
    }
}

// ---------------- launch ----------------

extern "C" void kernel_launch(void* const* d_in, const int* in_sizes, int n_in,
                              void* d_out, int out_size)
{
    const float* seq      = (const float*)d_in[0];
    const float* W1_txt_w = (const float*)d_in[1];
    const float* W1_txt_b = (const float*)d_in[2];
    const float* W1_vis_w = (const float*)d_in[3];
    const float* W1_vis_b = (const float*)d_in[4];
    const float* W2_vis_w = (const float*)d_in[5];
    const float* W2_vis_b = (const float*)d_in[6];
    const float* W1_sen_w = (const float*)d_in[7];
    const float* W1_sen_b = (const float*)d_in[8];
    const float* Wfcp_w   = (const float*)d_in[9];
    const float* Wfcp_b   = (const float*)d_in[10];
    const float* Wfc_w    = (const float*)d_in[11];
    const float* Wfc_b    = (const float*)d_in[12];
    float* out = (float*)d_out;

    float *p_vis1, *p_cat, *p_h256, *p_logits;
    cudaGetSymbolAddress((void**)&p_vis1,   g_vis1);
    cudaGetSymbolAddress((void**)&p_cat,    g_cat);
    cudaGetSymbolAddress((void**)&p_h256,   g_h256);
    cudaGetSymbolAddress((void**)&p_logits, g_logits);

    cudaFuncSetAttribute(mma_gemm, cudaFuncAttributeMaxDynamicSharedMemorySize, SMEMB);

    const int gy = MROWS / 128;   // 144

    // vis1: [M,2048] -> [M,512]   (64 k-chunks)
    mma_gemm<<<dim3(4, gy), 256, SMEMB>>>(
        seq + 512, 3076, W1_vis_w, W1_vis_b, p_vis1, 512, 2048, 64);

    // txt: [M,512] -> cat[:,0:128)
    mma_gemm<<<dim3(1, gy), 256, SMEMB>>>(
        seq + 0, 3076, W1_txt_w, W1_txt_b, p_cat + 0, 388, 512, 16);

    // vis2: [M,512] -> cat[:,128:256)
    mma_gemm<<<dim3(1, gy), 256, SMEMB>>>(
        p_vis1, 512, W2_vis_w, W2_vis_b, p_cat + 128, 388, 512, 16);

    // sen: [M,512] -> cat[:,260:388)
    mma_gemm<<<dim3(1, gy), 256, SMEMB>>>(
        seq + 2564, 3076, W1_sen_w, W1_sen_b, p_cat + 260, 388, 512, 16);

    // pos: relu -> cat[:,256:260)
    pos_relu_kernel<<<(MROWS * 4 + 255) / 256, 256>>>(seq, p_cat);

    // fc_pos: [M,388] -> [M,256]   (13 chunks, zero-padded tail)
    mma_gemm<<<dim3(2, gy), 256, SMEMB>>>(
        p_cat, 388, Wfcp_w, Wfcp_b, p_h256, 256, 388, 13);

    // fc: [M,256] -> [M,36], tanh
    fc_tanh_kernel<<<MROWS / 8, 288>>>(p_h256, Wfc_w, Wfc_b, p_logits);

    // sinkhorn
    sinkhorn_kernel<<<512, 64>>>(p_logits, out);
}

// round 14
// speedup vs baseline: 2.2566x; 1.0023x over previous
#include <cuda_runtime.h>
#include <cuda_fp16.h>
#include <math.h>
#include <stdint.h>

// ---------------------------------------------------------------------------
// SinkhornNetwork on GB300 — round 10: fp16-split mma.sync GEMMs, 512-thread
// CTAs (16 warps = 4/SMSP) to double latency hiding over round 8.
//   C = Ah*Wh + Al*Wh + Ah*Wl  (fp32 accumulate), W pre-scaled x32 so its
//   fp16 residuals stay normal; epilogue multiplies by 1/32.
// ---------------------------------------------------------------------------

static constexpr int MROWS = 512 * 36;   // 18432

__device__ float g_vis1[MROWS * 512];
__device__ float g_cat [MROWS * 388];
__device__ float g_h256[MROWS * 256];
__device__ float g_logits[MROWS * 36];

// ---------------- helpers ----------------

__device__ __forceinline__ uint32_t smem_u32(const void* p) {
    uint32_t a;
    asm("{ .reg .u64 t; cvta.to.shared.u64 t, %1; cvt.u32.u64 %0, t; }"
        : "=r"(a) : "l"(p));
    return a;
}

__device__ __forceinline__ void ldm4(uint32_t* d, uint32_t a) {
    asm volatile("ldmatrix.sync.aligned.m8n8.x4.shared.b16 {%0,%1,%2,%3}, [%4];"
        : "=r"(d[0]), "=r"(d[1]), "=r"(d[2]), "=r"(d[3]) : "r"(a));
}

__device__ __forceinline__ void mma16816(float* c, const uint32_t* a, const uint32_t* b) {
    asm volatile(
        "mma.sync.aligned.m16n8k16.row.col.f32.f16.f16.f32 "
        "{%0,%1,%2,%3},{%4,%5,%6,%7},{%8,%9},{%0,%1,%2,%3};"
        : "+f"(c[0]), "+f"(c[1]), "+f"(c[2]), "+f"(c[3])
        : "r"(a[0]), "r"(a[1]), "r"(a[2]), "r"(a[3]), "r"(b[0]), "r"(b[1]));
}

// fp16 split of two floats: hi = packed {lo16=f16(a), hi16=f16(b)},
// lo = packed residuals.
__device__ __forceinline__ void split2h(float a, float b, uint32_t& hi, uint32_t& lo) {
    uint32_t h;
    asm("cvt.rn.f16x2.f32 %0, %1, %2;" : "=r"(h) : "f"(b), "f"(a));
    float2 hf = __half22float2(*reinterpret_cast<const __half2*>(&h));
    float ra = a - hf.x;
    float rb = b - hf.y;
    uint32_t l;
    asm("cvt.rn.f16x2.f32 %0, %1, %2;" : "=r"(l) : "f"(rb), "f"(ra));
    hi = h; lo = l;
}

// ---------------- mma.sync GEMM (512 threads) ----------------
// C[128 x NT] tile = relu((A*W^T)*1/32 + bias), W pre-scaled x32.
// grid = (N/NT, M/128), 512 threads (16 warps: 4 m-rows x 4 n-cols).
// Warp tile: 32 x (NT/4). smem rows padded to 80B (conflict-free ldmatrix).

static constexpr int   ROWB   = 80;
static constexpr int   TILEA  = 128 * ROWB;     // 10240
static constexpr float WSCALE = 32.0f;
static constexpr float WINV   = 1.0f / 32.0f;

template<int NT>
__global__ void __launch_bounds__(512, 1) mma_gemm(
    const float* __restrict__ A, int lda,
    const float* __restrict__ W,
    const float* __restrict__ bias,
    float* __restrict__ C, int ldc,
    int K, int nch)
{
    constexpr int TILEW  = NT * ROWB;
    constexpr int STAGEB = 2 * TILEA + 2 * TILEW;
    constexpr int WN     = NT / 4;      // warp n extent (32 or 64)
    constexpr int NP     = WN / 16;     // n-tile pairs per warp (2 or 4)
    constexpr int WIT    = NT / 64;     // W float4 loads per thread (2 or 4)

    extern __shared__ char sm[];
    const uint32_t sbase = smem_u32(sm);

    const int tid  = threadIdx.x;
    const int lane = tid & 31;
    const int w    = tid >> 5;     // 0..15
    const int wm   = w & 3;        // warp row (x32)
    const int wn   = w >> 2;       // warp col (x WN)
    const long bm  = (long)blockIdx.y * 128;
    const long bn  = (long)blockIdx.x * NT;

    const float* Ap = A + bm * (long)lda;
    const float* Wp = W + bn * (long)K;

    float acc[2][2 * NP][4];
    #pragma unroll
    for (int mt = 0; mt < 2; mt++)
        #pragma unroll
        for (int nt = 0; nt < 2 * NP; nt++)
            #pragma unroll
            for (int q = 0; q < 4; q++)
                acc[mt][nt][q] = 0.0f;

    float4 ar[2], wr[WIT];   // staging registers for next chunk

    auto LDG = [&](int kc) {
        const int k0 = kc * 32;
        #pragma unroll
        for (int it = 0; it < 2; it++) {
            int idx = tid + it * 512;
            int row = idx >> 3;
            int k   = k0 + ((idx & 7) << 2);
            ar[it] = (k + 4 <= K)
                ? *reinterpret_cast<const float4*>(Ap + (size_t)row * lda + k)
                : make_float4(0.f, 0.f, 0.f, 0.f);
        }
        #pragma unroll
        for (int it = 0; it < WIT; it++) {
            int idx = tid + it * 512;
            int row = idx >> 3;
            int k   = k0 + ((idx & 7) << 2);
            wr[it] = (k + 4 <= K)
                ? *reinterpret_cast<const float4*>(Wp + (size_t)row * K + k)
                : make_float4(0.f, 0.f, 0.f, 0.f);
        }
    };

    auto STS = [&](int stg) {
        char* s = sm + stg * STAGEB;
        #pragma unroll
        for (int it = 0; it < 2; it++) {
            int idx = tid + it * 512;
            int row = idx >> 3;
            int off = row * ROWB + (((idx & 7) << 2) << 1);
            uint32_t h0, l0, h1, l1;
            split2h(ar[it].x, ar[it].y, h0, l0);
            split2h(ar[it].z, ar[it].w, h1, l1);
            *reinterpret_cast<uint2*>(s + off)         = make_uint2(h0, h1); // Ahi
            *reinterpret_cast<uint2*>(s + TILEA + off) = make_uint2(l0, l1); // Alo
        }
        #pragma unroll
        for (int it = 0; it < WIT; it++) {
            int idx = tid + it * 512;
            int row = idx >> 3;
            int off = row * ROWB + (((idx & 7) << 2) << 1);
            uint32_t h0, l0, h1, l1;
            split2h(wr[it].x * WSCALE, wr[it].y * WSCALE, h0, l0);
            split2h(wr[it].z * WSCALE, wr[it].w * WSCALE, h1, l1);
            *reinterpret_cast<uint2*>(s + 2 * TILEA + off)         = make_uint2(h0, h1); // Whi
            *reinterpret_cast<uint2*>(s + 2 * TILEA + TILEW + off) = make_uint2(l0, l1); // Wlo
        }
    };

    const int r8 = lane & 7;
    const int g  = lane >> 3;
    auto COMP = [&](int stg) {
        const uint32_t sb = sbase + (uint32_t)stg * STAGEB;
        #pragma unroll
        for (int s = 0; s < 2; s++) {       // two k16 steps per 32-col chunk
            uint32_t ah[2][4], al[2][4];
            #pragma unroll
            for (int mt = 0; mt < 2; mt++) {
                int row = wm * 32 + mt * 16 + ((g & 1) << 3) + r8;
                int co  = (s * 16 + ((g >> 1) << 3)) << 1;
                ldm4(ah[mt], sb + row * ROWB + co);
                ldm4(al[mt], sb + TILEA + row * ROWB + co);
            }
            #pragma unroll
            for (int np = 0; np < NP; np++) {
                int row = wn * WN + np * 16 + ((g >> 1) << 3) + r8;
                int co  = (s * 16 + ((g & 1) << 3)) << 1;
                uint32_t bh[2][2], bl[2][2], q[4];
                ldm4(q, sb + 2 * TILEA + row * ROWB + co);
                bh[0][0] = q[0]; bh[0][1] = q[1]; bh[1][0] = q[2]; bh[1][1] = q[3];
                ldm4(q, sb + 2 * TILEA + TILEW + row * ROWB + co);
                bl[0][0] = q[0]; bl[0][1] = q[1]; bl[1][0] = q[2]; bl[1][1] = q[3];
                #pragma unroll
                for (int mt = 0; mt < 2; mt++)
                    #pragma unroll
                    for (int h = 0; h < 2; h++) {
                        mma16816(acc[mt][np * 2 + h], ah[mt], bh[h]);   // hi*hi
                        mma16816(acc[mt][np * 2 + h], al[mt], bh[h]);   // lo*hi
                        mma16816(acc[mt][np * 2 + h], ah[mt], bl[h]);   // hi*lo
                    }
            }
        }
    };

    LDG(0);
    STS(0);
    __syncthreads();
    for (int i = 0; i < nch; i++) {
        if (i + 1 < nch) LDG(i + 1);
        COMP(i & 1);
        __syncthreads();
        if (i + 1 < nch) { STS((i + 1) & 1); __syncthreads(); }
    }

    // epilogue: *1/32, + bias, relu
    #pragma unroll
    for (int mt = 0; mt < 2; mt++) {
        const long r0 = bm + wm * 32 + mt * 16 + (lane >> 2);
        #pragma unroll
        for (int nt = 0; nt < 2 * NP; nt++) {
            const long col = bn + wn * WN + nt * 8 + (lane & 3) * 2;
            float2 bv = *reinterpret_cast<const float2*>(bias + col);
            float2 o0, o1;
            o0.x = fmaxf(fmaf(acc[mt][nt][0], WINV, bv.x), 0.f);
            o0.y = fmaxf(fmaf(acc[mt][nt][1], WINV, bv.y), 0.f);
            o1.x = fmaxf(fmaf(acc[mt][nt][2], WINV, bv.x), 0.f);
            o1.y = fmaxf(fmaf(acc[mt][nt][3], WINV, bv.y), 0.f);
            *reinterpret_cast<float2*>(C + r0 * (long)ldc + col)       = o0;
            *reinterpret_cast<float2*>(C + (r0 + 8) * (long)ldc + col) = o1;
        }
    }
}

static constexpr int SMEM128 = 2 * (2 * TILEA + 2 * 128 * ROWB);  //  81920
static constexpr int SMEM256 = 2 * (2 * TILEA + 2 * 256 * ROWB);  // 122880

// ---------------- small kernels ----------------

__global__ void pos_relu_kernel(const float* __restrict__ seq, float* __restrict__ cat)
{
    int idx = blockIdx.x * blockDim.x + threadIdx.x;
    if (idx < MROWS * 4) {
        int r = idx >> 2, c = idx & 3;
        float v = seq[(long)r * 3076 + 2560 + c];
        cat[(long)r * 388 + 256 + c] = fmaxf(v, 0.f);
    }
}

__global__ void __launch_bounds__(288) fc_tanh_kernel(
    const float* __restrict__ A,
    const float* __restrict__ W,
    const float* __restrict__ bias,
    float* __restrict__ out)
{
    __shared__ float Ws[36 * 260];
    __shared__ float Asm[8 * 260];
    __shared__ float bs[36];

    const int tid = threadIdx.x;
    const long rowBase = (long)blockIdx.x * 8;

    for (int i = tid; i < 36 * 256; i += 288) {
        int n = i >> 8, k = i & 255;
        Ws[n * 260 + k] = W[i];
    }
    for (int i = tid; i < 8 * 256; i += 288) {
        int r = i >> 8, k = i & 255;
        Asm[r * 260 + k] = A[(rowBase + r) * 256 + k];
    }
    if (tid < 36) bs[tid] = bias[tid];
    __syncthreads();

    const int r = tid / 36;
    const int n = tid % 36;
    if (r < 8) {
        const float* a = &Asm[r * 260];
        const float* wv = &Ws[n * 260];
        float s = bs[n];
        #pragma unroll 8
        for (int k = 0; k < 256; k++)
            s = fmaf(a[k], wv[k], s);
        out[(rowBase + r) * 36 + n] = tanhf(s);
    }
}

__global__ void __launch_bounds__(64) sinkhorn_kernel(
    const float* __restrict__ logits, float* __restrict__ out)
{
    const int b = blockIdx.x;
    const int j = threadIdx.x;
    __shared__ float xm[36][37];
    __shared__ float rowlse[36];
    float col[36];
    const bool act = (j < 36);

    if (act) {
        #pragma unroll
        for (int i = 0; i < 36; i++) {
            float t = logits[((long)b * 36 + i) * 36 + j];
            col[i] = expf(t * 20.0f);
        }
    }

    for (int it = 0; it < 20; it++) {
        if (act) {
            #pragma unroll
            for (int i = 0; i < 36; i++) xm[i][j] = col[i];
        }
        __syncthreads();
        if (act) {
            float m = -INFINITY;
            #pragma unroll
            for (int k = 0; k < 36; k++) m = fmaxf(m, xm[j][k]);
            float s = 0.f;
            #pragma unroll
            for (int k = 0; k < 36; k++) s += expf(xm[j][k] - m);
            rowlse[j] = m + logf(s);
        }
        __syncthreads();
        if (act) {
            #pragma unroll
            for (int i = 0; i < 36; i++) col[i] -= rowlse[i];
            float m = -INFINITY;
            #pragma unroll
            for (int i = 0; i < 36; i++) m = fmaxf(m, col[i]);
            float s = 0.f;
            #pragma unroll
            for (int i = 0; i < 36; i++) s += expf(col[i] - m);
            float l = m + logf(s);
            #pragma unroll
            for (int i = 0; i < 36; i++) col[i] -= l;
        }
        __syncthreads();
    }

    if (act) {
        #pragma unroll
        for (int i = 0; i < 36; i++)
            out[((long)b * 36 + i) * 36 + j] = expf(col[i]);
    }
}

// ---------------- launch ----------------

extern "C" void kernel_launch(void* const* d_in, const int* in_sizes, int n_in,
                              void* d_out, int out_size)
{
    const float* seq      = (const float*)d_in[0];
    const float* W1_txt_w = (const float*)d_in[1];
    const float* W1_txt_b = (const float*)d_in[2];
    const float* W1_vis_w = (const float*)d_in[3];
    const float* W1_vis_b = (const float*)d_in[4];
    const float* W2_vis_w = (const float*)d_in[5];
    const float* W2_vis_b = (const float*)d_in[6];
    const float* W1_sen_w = (const float*)d_in[7];
    const float* W1_sen_b = (const float*)d_in[8];
    const float* Wfcp_w   = (const float*)d_in[9];
    const float* Wfcp_b   = (const float*)d_in[10];
    const float* Wfc_w    = (const float*)d_in[11];
    const float* Wfc_b    = (const float*)d_in[12];
    float* out = (float*)d_out;

    float *p_vis1, *p_cat, *p_h256, *p_logits;
    cudaGetSymbolAddress((void**)&p_vis1,   g_vis1);
    cudaGetSymbolAddress((void**)&p_cat,    g_cat);
    cudaGetSymbolAddress((void**)&p_h256,   g_h256);
    cudaGetSymbolAddress((void**)&p_logits, g_logits);

    cudaFuncSetAttribute(mma_gemm<128>, cudaFuncAttributeMaxDynamicSharedMemorySize, SMEM128);
    cudaFuncSetAttribute(mma_gemm<256>, cudaFuncAttributeMaxDynamicSharedMemorySize, SMEM256);

    const int gy = MROWS / 128;   // 144

    // vis1: [M,2048] -> [M,512]
    mma_gemm<256><<<dim3(2, gy), 512, SMEM256>>>(
        seq + 512, 3076, W1_vis_w, W1_vis_b, p_vis1, 512, 2048, 64);

    // txt: [M,512] -> cat[:,0:128)
    mma_gemm<128><<<dim3(1, gy), 512, SMEM128>>>(
        seq + 0, 3076, W1_txt_w, W1_txt_b, p_cat + 0, 388, 512, 16);

    // vis2: [M,512] -> cat[:,128:256)
    mma_gemm<128><<<dim3(1, gy), 512, SMEM128>>>(
        p_vis1, 512, W2_vis_w, W2_vis_b, p_cat + 128, 388, 512, 16);

    // sen: [M,512] -> cat[:,260:388)
    mma_gemm<128><<<dim3(1, gy), 512, SMEM128>>>(
        seq + 2564, 3076, W1_sen_w, W1_sen_b, p_cat + 260, 388, 512, 16);

    // pos: relu -> cat[:,256:260)
    pos_relu_kernel<<<(MROWS * 4 + 255) / 256, 256>>>(seq, p_cat);

    // fc_pos: [M,388] -> [M,256]
    mma_gemm<256><<<dim3(1, gy), 512, SMEM256>>>(
        p_cat, 388, Wfcp_w, Wfcp_b, p_h256, 256, 388, 13);

    // fc: [M,256] -> [M,36], tanh
    fc_tanh_kernel<<<MROWS / 8, 288>>>(p_h256, Wfc_w, Wfc_b, p_logits);

    // sinkhorn
    sinkhorn_kernel<<<512, 64>>>(p_logits, out);
}